// round 2
// baseline (speedup 1.0000x reference)
#include <cuda_runtime.h>
#include <math.h>

// Problem constants
#define NN   10000          // nodes
#define EE   160000         // edges (before self loops)
#define ET   (EE + NN)      // edges + self loops
#define INC  768
#define HID  256
#define OUTC 256
#define NH   4
#define FDIM 1024           // NH*HID == NH*OUTC
#define EPS  1e-5f

// ---------------- device scratch (no allocations allowed) ----------------
__device__ float g_xh1[(size_t)NN * FDIM];   // 41 MB
__device__ float g_xh2[(size_t)NN * FDIM];   // 41 MB
__device__ float g_h1[(size_t)NN * HID];     // 10 MB
__device__ float g_s1[NN * NH];
__device__ float g_d1[NN * NH];
__device__ float g_s2[NN * NH];
__device__ float g_d2[NN * NH];
__device__ int   g_cnt[NN];
__device__ int   g_off[NN + 1];
__device__ int   g_cur[NN];
__device__ int   g_eid[ET];
__device__ float g_bnsum[2 * HID];
__device__ float g_bnscale[HID];
__device__ float g_bnshift[HID];

// ---------------- small utility kernels ----------------
__global__ void zero_kernel() {
    int i = blockIdx.x * blockDim.x + threadIdx.x;
    if (i < NN) g_cnt[i] = 0;
    if (i < 2 * HID) g_bnsum[i] = 0.f;
}

// edge_index is int32 (JAX without x64 coerces int64 -> int32)
__global__ void hist_kernel(const int* __restrict__ ei) {
    int e = blockIdx.x * blockDim.x + threadIdx.x;
    if (e >= ET) return;
    int d = (e < EE) ? ei[EE + e] : (e - EE);
    atomicAdd(&g_cnt[d], 1);
}

// Single-block exclusive scan over g_cnt -> g_off (and g_cur copy)
__global__ void scan_kernel() {
    __shared__ int wsum[32];
    const int T = 1024;
    const int PER = (NN + T - 1) / T;   // 10
    int tid = threadIdx.x;
    int base = tid * PER;
    int loc[PER];
    int tot = 0;
#pragma unroll
    for (int i = 0; i < PER; i++) {
        int idx = base + i;
        int v = (idx < NN) ? g_cnt[idx] : 0;
        loc[i] = v;
        tot += v;
    }
    int lane = tid & 31, warp = tid >> 5;
    int x = tot;
#pragma unroll
    for (int o = 1; o < 32; o <<= 1) {
        int y = __shfl_up_sync(~0u, x, o);
        if (lane >= o) x += y;
    }
    if (lane == 31) wsum[warp] = x;
    __syncthreads();
    if (warp == 0) {
        int w = wsum[lane];
#pragma unroll
        for (int o = 1; o < 32; o <<= 1) {
            int y = __shfl_up_sync(~0u, w, o);
            if (lane >= o) w += y;
        }
        wsum[lane] = w;
    }
    __syncthreads();
    int excl = x - tot + ((warp > 0) ? wsum[warp - 1] : 0);
    int run = excl;
#pragma unroll
    for (int i = 0; i < PER; i++) {
        int idx = base + i;
        if (idx < NN) { g_off[idx] = run; g_cur[idx] = run; }
        run += loc[i];
    }
    if (tid == T - 1) g_off[NN] = run;
}

__global__ void scatter_kernel(const int* __restrict__ ei) {
    int e = blockIdx.x * blockDim.x + threadIdx.x;
    if (e >= ET) return;
    int d = (e < EE) ? ei[EE + e] : (e - EE);
    int pos = atomicAdd(&g_cur[d], 1);
    g_eid[pos] = e;
}

// ---------------- GEMM: C[MxNn] = A[MxK] * B[KxNn], all row-major fp32 ----
#define BM 64
#define BN 64
#define BK 16
__global__ __launch_bounds__(256) void gemm_kernel(
    const float* __restrict__ A, const float* __restrict__ B,
    float* __restrict__ C, int M, int K, int Nn)
{
    __shared__ float As[BK][BM];
    __shared__ float Bs[BK][BN];
    int tid = threadIdx.x;
    int tx = tid & 15, ty = tid >> 4;
    int row0 = blockIdx.y * BM, col0 = blockIdx.x * BN;

    int a_row = tid >> 2;           // 0..63
    int a_k4 = (tid & 3) * 4;       // 0,4,8,12
    int b_k = tid >> 4;             // 0..15
    int b_n4 = (tid & 15) * 4;

    float acc[4][4];
#pragma unroll
    for (int i = 0; i < 4; i++)
#pragma unroll
        for (int j = 0; j < 4; j++) acc[i][j] = 0.f;

    for (int k0 = 0; k0 < K; k0 += BK) {
        float4 av = make_float4(0.f, 0.f, 0.f, 0.f);
        int gr = row0 + a_row;
        if (gr < M) av = *(const float4*)&A[(size_t)gr * K + k0 + a_k4];
        As[a_k4 + 0][a_row] = av.x;
        As[a_k4 + 1][a_row] = av.y;
        As[a_k4 + 2][a_row] = av.z;
        As[a_k4 + 3][a_row] = av.w;
        float4 bv = *(const float4*)&B[(size_t)(k0 + b_k) * Nn + col0 + b_n4];
        *(float4*)&Bs[b_k][b_n4] = bv;
        __syncthreads();
#pragma unroll
        for (int kk = 0; kk < BK; kk++) {
            float4 ar = *(const float4*)&As[kk][ty * 4];
            float4 br = *(const float4*)&Bs[kk][tx * 4];
            float a4[4] = {ar.x, ar.y, ar.z, ar.w};
            float b4[4] = {br.x, br.y, br.z, br.w};
#pragma unroll
            for (int i = 0; i < 4; i++)
#pragma unroll
                for (int j = 0; j < 4; j++) acc[i][j] += a4[i] * b4[j];
        }
        __syncthreads();
    }
#pragma unroll
    for (int i = 0; i < 4; i++) {
        int gr = row0 + ty * 4 + i;
        if (gr < M) {
            float4 v = make_float4(acc[i][0], acc[i][1], acc[i][2], acc[i][3]);
            *(float4*)&C[(size_t)gr * Nn + col0 + tx * 4] = v;
        }
    }
}

// ---------------- attention logits: s[n,h], d[n,h] ----------------
__global__ __launch_bounds__(128) void sd_kernel(
    const float* __restrict__ xh, const float* __restrict__ a_src,
    const float* __restrict__ a_dst, float* __restrict__ s, float* __restrict__ d)
{
    int n = blockIdx.x;
    int w = threadIdx.x >> 5;      // head
    int lane = threadIdx.x & 31;
    const float* row = xh + (size_t)n * FDIM + w * 256;
    const float* as = a_src + w * 256;
    const float* ad = a_dst + w * 256;
    float ss = 0.f, dd = 0.f;
#pragma unroll
    for (int c = lane; c < 256; c += 32) {
        float v = row[c];
        ss += v * as[c];
        dd += v * ad[c];
    }
#pragma unroll
    for (int o = 16; o; o >>= 1) {
        ss += __shfl_xor_sync(~0u, ss, o);
        dd += __shfl_xor_sync(~0u, dd, o);
    }
    if (lane == 0) {
        s[n * NH + w] = ss;
        d[n * NH + w] = dd;
    }
}

// ---------------- GAT aggregation: one block per dst node ----------------
__global__ __launch_bounds__(256) void gat_aggregate(
    const float* __restrict__ xh, const float* __restrict__ sarr,
    const float* __restrict__ darr, const int* __restrict__ ei,
    const float* __restrict__ bias, float* __restrict__ out)
{
    __shared__ float sh_max[NH], sh_rden[NH], sh_d[NH];
    __shared__ int   sh_src[64];
    __shared__ float sh_alpha[64 * NH];
    __shared__ float sh_acc[FDIM];

    int n = blockIdx.x;
    int t = threadIdx.x;
    int beg = g_off[n], end = g_off[n + 1];
    int deg = end - beg;

    if (t < 32) {
        int lane = t;
        float4 dd4 = *(const float4*)(darr + n * NH);
        float dh[NH] = {dd4.x, dd4.y, dd4.z, dd4.w};
        float mx[NH] = {-1e30f, -1e30f, -1e30f, -1e30f};
        for (int i = lane; i < deg; i += 32) {
            int e = g_eid[beg + i];
            int si = (e < EE) ? ei[e] : (e - EE);
            float4 sv = *(const float4*)(sarr + si * NH);
            float v;
            v = sv.x + dh[0]; v = v > 0.f ? v : 0.2f * v; mx[0] = fmaxf(mx[0], v);
            v = sv.y + dh[1]; v = v > 0.f ? v : 0.2f * v; mx[1] = fmaxf(mx[1], v);
            v = sv.z + dh[2]; v = v > 0.f ? v : 0.2f * v; mx[2] = fmaxf(mx[2], v);
            v = sv.w + dh[3]; v = v > 0.f ? v : 0.2f * v; mx[3] = fmaxf(mx[3], v);
        }
#pragma unroll
        for (int o = 16; o; o >>= 1) {
#pragma unroll
            for (int h = 0; h < NH; h++)
                mx[h] = fmaxf(mx[h], __shfl_xor_sync(~0u, mx[h], o));
        }
        float sm[NH] = {0.f, 0.f, 0.f, 0.f};
        for (int i = lane; i < deg; i += 32) {
            int e = g_eid[beg + i];
            int si = (e < EE) ? ei[e] : (e - EE);
            float4 sv = *(const float4*)(sarr + si * NH);
            float v;
            v = sv.x + dh[0]; v = v > 0.f ? v : 0.2f * v; sm[0] += expf(v - mx[0]);
            v = sv.y + dh[1]; v = v > 0.f ? v : 0.2f * v; sm[1] += expf(v - mx[1]);
            v = sv.z + dh[2]; v = v > 0.f ? v : 0.2f * v; sm[2] += expf(v - mx[2]);
            v = sv.w + dh[3]; v = v > 0.f ? v : 0.2f * v; sm[3] += expf(v - mx[3]);
        }
#pragma unroll
        for (int o = 16; o; o >>= 1) {
#pragma unroll
            for (int h = 0; h < NH; h++)
                sm[h] += __shfl_xor_sync(~0u, sm[h], o);
        }
        if (lane == 0) {
#pragma unroll
            for (int h = 0; h < NH; h++) {
                sh_max[h] = mx[h];
                sh_rden[h] = 1.f / sm[h];
                sh_d[h] = dh[h];
            }
        }
    }
    __syncthreads();

    float a0 = 0.f, a1 = 0.f, a2 = 0.f, a3 = 0.f;
    int hh = t >> 6;   // head of flat indices 4t..4t+3

    for (int c0 = 0; c0 < deg; c0 += 64) {
        int cn = min(64, deg - c0);
        int te = t >> 2, th = t & 3;
        if (te < cn) {
            int e = g_eid[beg + c0 + te];
            int si = (e < EE) ? ei[e] : (e - EE);
            if (th == 0) sh_src[te] = si;
            float v = sarr[si * NH + th] + sh_d[th];
            v = v > 0.f ? v : 0.2f * v;
            sh_alpha[te * NH + th] = expf(v - sh_max[th]) * sh_rden[th];
        }
        __syncthreads();
        for (int j = 0; j < cn; j++) {
            int si = sh_src[j];
            float al = sh_alpha[j * NH + hh];
            float4 xv = *(const float4*)(xh + (size_t)si * FDIM + t * 4);
            a0 += al * xv.x; a1 += al * xv.y; a2 += al * xv.z; a3 += al * xv.w;
        }
        __syncthreads();
    }

    sh_acc[t * 4 + 0] = a0;
    sh_acc[t * 4 + 1] = a1;
    sh_acc[t * 4 + 2] = a2;
    sh_acc[t * 4 + 3] = a3;
    __syncthreads();
    // head mean + bias; t = channel
    float r = 0.25f * (sh_acc[t] + sh_acc[256 + t] + sh_acc[512 + t] + sh_acc[768 + t]) + bias[t];
    out[(size_t)n * 256 + t] = r;
}

// ---------------- BatchNorm ----------------
__global__ __launch_bounds__(256) void bn_partial() {
    int t = threadIdx.x;  // channel
    float sum = 0.f, sq = 0.f;
    for (int n = blockIdx.x; n < NN; n += gridDim.x) {
        float v = g_h1[(size_t)n * HID + t];
        sum += v;
        sq += v * v;
    }
    atomicAdd(&g_bnsum[t], sum);
    atomicAdd(&g_bnsum[HID + t], sq);
}

__global__ __launch_bounds__(256) void bn_finalize(
    const float* __restrict__ gamma, const float* __restrict__ beta)
{
    int t = threadIdx.x;
    float mu = g_bnsum[t] / (float)NN;
    float var = g_bnsum[HID + t] / (float)NN - mu * mu;
    float sc = gamma[t] * rsqrtf(var + EPS);
    g_bnscale[t] = sc;
    g_bnshift[t] = beta[t] - mu * sc;
}

__global__ __launch_bounds__(256) void bn_apply() {
    int i = blockIdx.x * blockDim.x + threadIdx.x;
    if (i >= NN * HID) return;
    int c = i & (HID - 1);
    float v = g_h1[i] * g_bnscale[c] + g_bnshift[c];
    g_h1[i] = v > 0.f ? v : 0.f;
}

// ---------------- launch ----------------
extern "C" void kernel_launch(void* const* d_in, const int* in_sizes, int n_in,
                              void* d_out, int out_size)
{
    const float* x        = (const float*)d_in[0];
    const int*   ei       = (const int*)d_in[1];
    const float* W1       = (const float*)d_in[2];
    const float* as1      = (const float*)d_in[3];
    const float* ad1      = (const float*)d_in[4];
    const float* b1       = (const float*)d_in[5];
    const float* gamma    = (const float*)d_in[6];
    const float* beta     = (const float*)d_in[7];
    const float* W2       = (const float*)d_in[8];
    const float* as2      = (const float*)d_in[9];
    const float* ad2      = (const float*)d_in[10];
    const float* b2       = (const float*)d_in[11];
    float* out            = (float*)d_out;

    float* xh1; cudaGetSymbolAddress((void**)&xh1, g_xh1);
    float* xh2; cudaGetSymbolAddress((void**)&xh2, g_xh2);
    float* h1;  cudaGetSymbolAddress((void**)&h1,  g_h1);
    float* s1;  cudaGetSymbolAddress((void**)&s1,  g_s1);
    float* d1;  cudaGetSymbolAddress((void**)&d1,  g_d1);
    float* s2;  cudaGetSymbolAddress((void**)&s2,  g_s2);
    float* d2;  cudaGetSymbolAddress((void**)&d2,  g_d2);

    // CSR build + zero accumulators
    zero_kernel<<<(NN + 255) / 256, 256>>>();
    hist_kernel<<<(ET + 255) / 256, 256>>>(ei);
    scan_kernel<<<1, 1024>>>();
    scatter_kernel<<<(ET + 255) / 256, 256>>>(ei);

    // Layer 1
    dim3 ggrid1(FDIM / BN, (NN + BM - 1) / BM);
    gemm_kernel<<<ggrid1, 256>>>(x, W1, xh1, NN, INC, FDIM);
    sd_kernel<<<NN, 128>>>(xh1, as1, ad1, s1, d1);
    gat_aggregate<<<NN, 256>>>(xh1, s1, d1, ei, b1, h1);

    // BN + ReLU
    bn_partial<<<296, 256>>>();
    bn_finalize<<<1, 256>>>(gamma, beta);
    bn_apply<<<(NN * HID + 255) / 256, 256>>>();

    // Layer 2
    dim3 ggrid2(FDIM / BN, (NN + BM - 1) / BM);
    gemm_kernel<<<ggrid2, 256>>>(h1, W2, xh2, NN, HID, FDIM);
    sd_kernel<<<NN, 128>>>(xh2, as2, ad2, s2, d2);
    gat_aggregate<<<NN, 256>>>(xh2, s2, d2, ei, b2, out);
}

// round 4
// speedup vs baseline: 1.8183x; 1.8183x over previous
#include <cuda_runtime.h>
#include <cuda_bf16.h>
#include <cstdint>
#include <math.h>

// Problem constants
#define NN   10000          // nodes
#define EE   160000         // edges (before self loops)
#define ET   (EE + NN)      // edges + self loops
#define INC  768
#define HID  256
#define NH   4
#define FDIM 1024           // NH*HID == NH*OUTC
#define EPS  1e-5f

// ---------------- device scratch (no allocations allowed) ----------------
__device__ float g_xh1[(size_t)NN * FDIM];   // 41 MB
__device__ float g_xh2[(size_t)NN * FDIM];   // 41 MB
__device__ float g_h1[(size_t)NN * HID];     // 10 MB
__device__ float g_s1[NN * NH];
__device__ float g_d1[NN * NH];
__device__ float g_s2[NN * NH];
__device__ float g_d2[NN * NH];
__device__ int   g_cnt[NN];
__device__ int   g_off[NN + 1];
__device__ int   g_cur[NN];
__device__ int   g_eid[ET];
__device__ float g_bnsum[2 * HID];
__device__ float g_bnscale[HID];
__device__ float g_bnshift[HID];

// ================= mma.sync GEMM (baseline PTX, works on compute_103) ====
__device__ __forceinline__ uint32_t smem_u32(const void* p) {
    uint32_t a;
    asm("{ .reg .u64 t; cvta.to.shared.u64 t, %1; cvt.u32.u64 %0, t; }" : "=r"(a) : "l"(p));
    return a;
}

#define LDSM4(r0, r1, r2, r3, addr) \
    asm volatile("ldmatrix.sync.aligned.m8n8.x4.shared.b16 {%0,%1,%2,%3}, [%4];" \
        : "=r"(r0), "=r"(r1), "=r"(r2), "=r"(r3) : "r"(addr))

#define MMA_BF16(c, a0, a1, a2, a3, b0, b1) \
    asm volatile("mma.sync.aligned.m16n8k16.row.col.f32.bf16.bf16.f32 " \
        "{%0,%1,%2,%3}, {%4,%5,%6,%7}, {%8,%9}, {%0,%1,%2,%3};" \
        : "+f"((c)[0]), "+f"((c)[1]), "+f"((c)[2]), "+f"((c)[3]) \
        : "r"(a0), "r"(a1), "r"(a2), "r"(a3), "r"(b0), "r"(b1))

#define STS_V2(addr, w0, w1) \
    asm volatile("st.shared.v2.b32 [%0], {%1,%2};" :: "r"(addr), "r"(w0), "r"(w1) : "memory")

// Split two fp32 values into packed bf16x2 hi and residual lo words.
// word layout: low 16 bits = first (even-k) element — matches mma fragment order.
__device__ __forceinline__ void pack2(float x0, float x1, uint32_t& hi, uint32_t& lo) {
    __nv_bfloat162 h = __floats2bfloat162_rn(x0, x1);
    uint32_t u = *reinterpret_cast<uint32_t*>(&h);
    float f0 = __uint_as_float(u << 16);
    float f1 = __uint_as_float(u & 0xffff0000u);
    __nv_bfloat162 l = __floats2bfloat162_rn(x0 - f0, x1 - f1);
    hi = u;
    lo = *reinterpret_cast<uint32_t*>(&l);
}

// SMEM layout per buffer (stride 40960B):  rows padded to 80B (64B data + 16B)
//   Ahi @ 0      (128 x 80)
//   Alo @ 10240
//   Bhi @ 20480  (B transposed: [n][k])
//   Blo @ 30720
#define GEMM_SMEM_BYTES 81920

__device__ __forceinline__ void gemm_stage(
    const float* __restrict__ A, const float* __restrict__ B,
    int M, int K, int m0, int n0, int k0, uint32_t sb, int buf)
{
    uint32_t base = sb + (uint32_t)buf * 40960u;
    int t = threadIdx.x;
    // ---- A tile: 128 rows x 32 k ----
#pragma unroll
    for (int i = 0; i < 4; i++) {
        int idx = t + 256 * i;           // 0..1023
        int m = idx >> 3, kq = (idx & 7) * 4;
        float4 v = make_float4(0.f, 0.f, 0.f, 0.f);
        if (m0 + m < M) v = *(const float4*)(A + (size_t)(m0 + m) * K + k0 + kq);
        uint32_t h0, l0, h1, l1;
        pack2(v.x, v.y, h0, l0);
        pack2(v.z, v.w, h1, l1);
        uint32_t off = (uint32_t)(m * 80 + kq * 2);
        STS_V2(base + off, h0, h1);
        STS_V2(base + 10240u + off, l0, l1);
    }
    // ---- B tile (transpose to [n][k]): 32 k x 128 n ----
    int n = t & 127;
    int khalf = (t >> 7) * 4;
#pragma unroll
    for (int kb = 0; kb < 4; kb++) {
        int kk = kb * 8 + khalf;
        const float* bp = B + (size_t)(k0 + kk) * FDIM + n0 + n;
        float b0 = bp[0], b1 = bp[FDIM], b2 = bp[2 * FDIM], b3 = bp[3 * FDIM];
        uint32_t h0, l0, h1, l1;
        pack2(b0, b1, h0, l0);
        pack2(b2, b3, h1, l1);
        uint32_t off = (uint32_t)(n * 80 + kk * 2);
        STS_V2(base + 20480u + off, h0, h1);
        STS_V2(base + 30720u + off, l0, l1);
    }
}

// C[M x 1024] = A[M x K] * B[K x 1024]; fp32 I/O, bf16x3 emulated fp32 MMA.
// grid = (8, ceil(M/128)), 256 threads.
__global__ __launch_bounds__(256) void gemm_mma(
    const float* __restrict__ A, const float* __restrict__ B,
    float* __restrict__ C, int M, int K)
{
    extern __shared__ char smem[];
    uint32_t sb = smem_u32(smem);
    int t = threadIdx.x, lane = t & 31, w = t >> 5;
    int m0 = blockIdx.y * 128, n0 = blockIdx.x * 128;
    int wm = (w & 1) * 64, wn = (w >> 1) * 32;

    // ldmatrix per-lane address offsets
    int aRow = (lane & 7) + ((lane >> 3) & 1) * 8;
    uint32_t aOff = (uint32_t)((wm + aRow) * 80 + ((lane >> 4) & 1) * 16);
    int bRow = (lane & 7) + (lane >> 4) * 8;
    uint32_t bOff = (uint32_t)((wn + bRow) * 80 + ((lane >> 3) & 1) * 16);

    float acc[4][4][4];
#pragma unroll
    for (int mi = 0; mi < 4; mi++)
#pragma unroll
        for (int ni = 0; ni < 4; ni++)
#pragma unroll
            for (int j = 0; j < 4; j++) acc[mi][ni][j] = 0.f;

    const int nst = K / 32;
    gemm_stage(A, B, M, K, m0, n0, 0, sb, 0);
    __syncthreads();

    for (int s = 0; s < nst; s++) {
        if (s + 1 < nst) gemm_stage(A, B, M, K, m0, n0, (s + 1) * 32, sb, (s + 1) & 1);
        uint32_t base = sb + (uint32_t)(s & 1) * 40960u;
#pragma unroll
        for (int ks = 0; ks < 2; ks++) {
            uint32_t kb = (uint32_t)(ks * 32);
            uint32_t bh[8], bl[8];
#pragma unroll
            for (int np = 0; np < 2; np++) {
                uint32_t ad = base + 20480u + bOff + (uint32_t)(np * 1280) + kb;
                LDSM4(bh[np * 4 + 0], bh[np * 4 + 1], bh[np * 4 + 2], bh[np * 4 + 3], ad);
                LDSM4(bl[np * 4 + 0], bl[np * 4 + 1], bl[np * 4 + 2], bl[np * 4 + 3], ad + 10240u);
            }
#pragma unroll
            for (int mi = 0; mi < 4; mi++) {
                uint32_t ah0, ah1, ah2, ah3, al0, al1, al2, al3;
                uint32_t ad = base + aOff + (uint32_t)(mi * 1280) + kb;
                LDSM4(ah0, ah1, ah2, ah3, ad);
                LDSM4(al0, al1, al2, al3, ad + 10240u);
#pragma unroll
                for (int ni = 0; ni < 4; ni++) {
                    MMA_BF16(acc[mi][ni], ah0, ah1, ah2, ah3, bh[ni * 2 + 0], bh[ni * 2 + 1]);
                    MMA_BF16(acc[mi][ni], ah0, ah1, ah2, ah3, bl[ni * 2 + 0], bl[ni * 2 + 1]);
                    MMA_BF16(acc[mi][ni], al0, al1, al2, al3, bh[ni * 2 + 0], bh[ni * 2 + 1]);
                }
            }
        }
        __syncthreads();
    }

    // ---- epilogue: direct register -> global stores ----
#pragma unroll
    for (int mi = 0; mi < 4; mi++) {
#pragma unroll
        for (int ni = 0; ni < 4; ni++) {
            int r = m0 + wm + mi * 16 + (lane >> 2);
            int c = n0 + wn + ni * 8 + (lane & 3) * 2;
            if (r < M)
                *(float2*)(C + (size_t)r * FDIM + c) = make_float2(acc[mi][ni][0], acc[mi][ni][1]);
            if (r + 8 < M)
                *(float2*)(C + (size_t)(r + 8) * FDIM + c) = make_float2(acc[mi][ni][2], acc[mi][ni][3]);
        }
    }
}

// ---------------- small utility kernels ----------------
__global__ void zero_kernel() {
    int i = blockIdx.x * blockDim.x + threadIdx.x;
    if (i < NN) g_cnt[i] = 0;
    if (i < 2 * HID) g_bnsum[i] = 0.f;
}

__global__ void hist_kernel(const int* __restrict__ ei) {
    int e = blockIdx.x * blockDim.x + threadIdx.x;
    if (e >= ET) return;
    int d = (e < EE) ? ei[EE + e] : (e - EE);
    atomicAdd(&g_cnt[d], 1);
}

__global__ void scan_kernel() {
    __shared__ int wsum[32];
    const int T = 1024;
    const int PER = (NN + T - 1) / T;
    int tid = threadIdx.x;
    int base = tid * PER;
    int loc[PER];
    int tot = 0;
#pragma unroll
    for (int i = 0; i < PER; i++) {
        int idx = base + i;
        int v = (idx < NN) ? g_cnt[idx] : 0;
        loc[i] = v; tot += v;
    }
    int lane = tid & 31, warp = tid >> 5;
    int x = tot;
#pragma unroll
    for (int o = 1; o < 32; o <<= 1) {
        int y = __shfl_up_sync(~0u, x, o);
        if (lane >= o) x += y;
    }
    if (lane == 31) wsum[warp] = x;
    __syncthreads();
    if (warp == 0) {
        int v = wsum[lane];
#pragma unroll
        for (int o = 1; o < 32; o <<= 1) {
            int y = __shfl_up_sync(~0u, v, o);
            if (lane >= o) v += y;
        }
        wsum[lane] = v;
    }
    __syncthreads();
    int excl = x - tot + ((warp > 0) ? wsum[warp - 1] : 0);
    int run = excl;
#pragma unroll
    for (int i = 0; i < PER; i++) {
        int idx = base + i;
        if (idx < NN) { g_off[idx] = run; g_cur[idx] = run; }
        run += loc[i];
    }
    if (tid == T - 1) g_off[NN] = run;
}

__global__ void scatter_kernel(const int* __restrict__ ei) {
    int e = blockIdx.x * blockDim.x + threadIdx.x;
    if (e >= ET) return;
    int d = (e < EE) ? ei[EE + e] : (e - EE);
    int pos = atomicAdd(&g_cur[d], 1);
    g_eid[pos] = e;
}

// ---------------- attention logits ----------------
__global__ __launch_bounds__(128) void sd_kernel(
    const float* __restrict__ xh, const float* __restrict__ a_src,
    const float* __restrict__ a_dst, float* __restrict__ s, float* __restrict__ d)
{
    int n = blockIdx.x;
    int w = threadIdx.x >> 5;
    int lane = threadIdx.x & 31;
    const float* row = xh + (size_t)n * FDIM + w * 256;
    const float* as = a_src + w * 256;
    const float* ad = a_dst + w * 256;
    float ss = 0.f, dd = 0.f;
#pragma unroll
    for (int c = lane; c < 256; c += 32) {
        float v = row[c];
        ss += v * as[c];
        dd += v * ad[c];
    }
#pragma unroll
    for (int o = 16; o; o >>= 1) {
        ss += __shfl_xor_sync(~0u, ss, o);
        dd += __shfl_xor_sync(~0u, dd, o);
    }
    if (lane == 0) { s[n * NH + w] = ss; d[n * NH + w] = dd; }
}

// ---------------- GAT aggregation: one block per dst node ----------------
__global__ __launch_bounds__(256) void gat_aggregate(
    const float* __restrict__ xh, const float* __restrict__ sarr,
    const float* __restrict__ darr, const int* __restrict__ ei,
    const float* __restrict__ bias, float* __restrict__ out)
{
    __shared__ float sh_max[NH], sh_rden[NH], sh_d[NH];
    __shared__ int   sh_src[64];
    __shared__ float sh_alpha[64 * NH];
    __shared__ float sh_acc[FDIM];

    int n = blockIdx.x;
    int t = threadIdx.x;
    int beg = g_off[n], end = g_off[n + 1];
    int deg = end - beg;

    if (t < 32) {
        int lane = t;
        float4 dd4 = *(const float4*)(darr + n * NH);
        float dh[NH] = {dd4.x, dd4.y, dd4.z, dd4.w};
        float mx[NH] = {-1e30f, -1e30f, -1e30f, -1e30f};
        for (int i = lane; i < deg; i += 32) {
            int e = g_eid[beg + i];
            int si = (e < EE) ? ei[e] : (e - EE);
            float4 sv = *(const float4*)(sarr + si * NH);
            float v;
            v = sv.x + dh[0]; v = v > 0.f ? v : 0.2f * v; mx[0] = fmaxf(mx[0], v);
            v = sv.y + dh[1]; v = v > 0.f ? v : 0.2f * v; mx[1] = fmaxf(mx[1], v);
            v = sv.z + dh[2]; v = v > 0.f ? v : 0.2f * v; mx[2] = fmaxf(mx[2], v);
            v = sv.w + dh[3]; v = v > 0.f ? v : 0.2f * v; mx[3] = fmaxf(mx[3], v);
        }
#pragma unroll
        for (int o = 16; o; o >>= 1)
#pragma unroll
            for (int h = 0; h < NH; h++)
                mx[h] = fmaxf(mx[h], __shfl_xor_sync(~0u, mx[h], o));
        float sm[NH] = {0.f, 0.f, 0.f, 0.f};
        for (int i = lane; i < deg; i += 32) {
            int e = g_eid[beg + i];
            int si = (e < EE) ? ei[e] : (e - EE);
            float4 sv = *(const float4*)(sarr + si * NH);
            float v;
            v = sv.x + dh[0]; v = v > 0.f ? v : 0.2f * v; sm[0] += expf(v - mx[0]);
            v = sv.y + dh[1]; v = v > 0.f ? v : 0.2f * v; sm[1] += expf(v - mx[1]);
            v = sv.z + dh[2]; v = v > 0.f ? v : 0.2f * v; sm[2] += expf(v - mx[2]);
            v = sv.w + dh[3]; v = v > 0.f ? v : 0.2f * v; sm[3] += expf(v - mx[3]);
        }
#pragma unroll
        for (int o = 16; o; o >>= 1)
#pragma unroll
            for (int h = 0; h < NH; h++)
                sm[h] += __shfl_xor_sync(~0u, sm[h], o);
        if (lane == 0) {
#pragma unroll
            for (int h = 0; h < NH; h++) {
                sh_max[h] = mx[h];
                sh_rden[h] = 1.f / sm[h];
                sh_d[h] = dh[h];
            }
        }
    }
    __syncthreads();

    float a0 = 0.f, a1 = 0.f, a2 = 0.f, a3 = 0.f;
    int hh = t >> 6;

    for (int c0 = 0; c0 < deg; c0 += 64) {
        int cn = min(64, deg - c0);
        int te = t >> 2, th = t & 3;
        if (te < cn) {
            int e = g_eid[beg + c0 + te];
            int si = (e < EE) ? ei[e] : (e - EE);
            if (th == 0) sh_src[te] = si;
            float v = sarr[si * NH + th] + sh_d[th];
            v = v > 0.f ? v : 0.2f * v;
            sh_alpha[te * NH + th] = expf(v - sh_max[th]) * sh_rden[th];
        }
        __syncthreads();
        for (int j = 0; j < cn; j++) {
            int si = sh_src[j];
            float al = sh_alpha[j * NH + hh];
            float4 xv = *(const float4*)(xh + (size_t)si * FDIM + t * 4);
            a0 += al * xv.x; a1 += al * xv.y; a2 += al * xv.z; a3 += al * xv.w;
        }
        __syncthreads();
    }

    sh_acc[t * 4 + 0] = a0;
    sh_acc[t * 4 + 1] = a1;
    sh_acc[t * 4 + 2] = a2;
    sh_acc[t * 4 + 3] = a3;
    __syncthreads();
    float r = 0.25f * (sh_acc[t] + sh_acc[256 + t] + sh_acc[512 + t] + sh_acc[768 + t]) + bias[t];
    out[(size_t)n * 256 + t] = r;
}

// ---------------- BatchNorm ----------------
__global__ __launch_bounds__(256) void bn_partial() {
    int t = threadIdx.x;
    float sum = 0.f, sq = 0.f;
    for (int n = blockIdx.x; n < NN; n += gridDim.x) {
        float v = g_h1[(size_t)n * HID + t];
        sum += v; sq += v * v;
    }
    atomicAdd(&g_bnsum[t], sum);
    atomicAdd(&g_bnsum[HID + t], sq);
}

__global__ __launch_bounds__(256) void bn_finalize(
    const float* __restrict__ gamma, const float* __restrict__ beta)
{
    int t = threadIdx.x;
    float mu = g_bnsum[t] / (float)NN;
    float var = g_bnsum[HID + t] / (float)NN - mu * mu;
    float sc = gamma[t] * rsqrtf(var + EPS);
    g_bnscale[t] = sc;
    g_bnshift[t] = beta[t] - mu * sc;
}

__global__ __launch_bounds__(256) void bn_apply() {
    int i = blockIdx.x * blockDim.x + threadIdx.x;
    if (i >= NN * HID) return;
    int c = i & (HID - 1);
    float v = g_h1[i] * g_bnscale[c] + g_bnshift[c];
    g_h1[i] = v > 0.f ? v : 0.f;
}

// ---------------- launch ----------------
extern "C" void kernel_launch(void* const* d_in, const int* in_sizes, int n_in,
                              void* d_out, int out_size)
{
    const float* x     = (const float*)d_in[0];
    const int*   ei    = (const int*)d_in[1];
    const float* W1    = (const float*)d_in[2];
    const float* as1   = (const float*)d_in[3];
    const float* ad1   = (const float*)d_in[4];
    const float* b1    = (const float*)d_in[5];
    const float* gamma = (const float*)d_in[6];
    const float* beta  = (const float*)d_in[7];
    const float* W2    = (const float*)d_in[8];
    const float* as2   = (const float*)d_in[9];
    const float* ad2   = (const float*)d_in[10];
    const float* b2    = (const float*)d_in[11];
    float* out         = (float*)d_out;

    float* xh1; cudaGetSymbolAddress((void**)&xh1, g_xh1);
    float* xh2; cudaGetSymbolAddress((void**)&xh2, g_xh2);
    float* h1;  cudaGetSymbolAddress((void**)&h1,  g_h1);
    float* s1;  cudaGetSymbolAddress((void**)&s1,  g_s1);
    float* d1;  cudaGetSymbolAddress((void**)&d1,  g_d1);
    float* s2;  cudaGetSymbolAddress((void**)&s2,  g_s2);
    float* d2;  cudaGetSymbolAddress((void**)&d2,  g_d2);

    cudaFuncSetAttribute(gemm_mma, cudaFuncAttributeMaxDynamicSharedMemorySize,
                         GEMM_SMEM_BYTES);

    // CSR build + zero accumulators
    zero_kernel<<<(NN + 255) / 256, 256>>>();
    hist_kernel<<<(ET + 255) / 256, 256>>>(ei);
    scan_kernel<<<1, 1024>>>();
    scatter_kernel<<<(ET + 255) / 256, 256>>>(ei);

    dim3 ggrid(FDIM / 128, (NN + 127) / 128);

    // Layer 1
    gemm_mma<<<ggrid, 256, GEMM_SMEM_BYTES>>>(x, W1, xh1, NN, INC);
    sd_kernel<<<NN, 128>>>(xh1, as1, ad1, s1, d1);
    gat_aggregate<<<NN, 256>>>(xh1, s1, d1, ei, b1, h1);

    // BN + ReLU
    bn_partial<<<296, 256>>>();
    bn_finalize<<<1, 256>>>(gamma, beta);
    bn_apply<<<(NN * HID + 255) / 256, 256>>>();

    // Layer 2
    gemm_mma<<<ggrid, 256, GEMM_SMEM_BYTES>>>(h1, W2, xh2, NN, HID);
    sd_kernel<<<NN, 128>>>(xh2, as2, ad2, s2, d2);
    gat_aggregate<<<NN, 256>>>(xh2, s2, d2, ei, b2, out);
}

// round 5
// speedup vs baseline: 2.1997x; 1.2097x over previous
#include <cuda_runtime.h>
#include <cuda_bf16.h>
#include <cstdint>
#include <math.h>

// Problem constants
#define NN   10000          // nodes
#define EE   160000         // edges (before self loops)
#define ET   (EE + NN)      // edges + self loops
#define INC  768
#define HID  256
#define NH   4
#define FDIM 1024           // NH*HID == NH*OUTC
#define EPS  1e-5f

// ---------------- device scratch (no allocations allowed) ----------------
__device__ float g_xh1[(size_t)NN * FDIM];   // 41 MB
__device__ float g_xh2[(size_t)NN * FDIM];   // 41 MB
__device__ float g_h1[(size_t)NN * HID];     // 10 MB
__device__ float g_s1[NN * NH];
__device__ float g_d1[NN * NH];
__device__ float g_s2[NN * NH];
__device__ float g_d2[NN * NH];
__device__ int   g_cnt[NN];
__device__ int   g_off[NN + 1];
__device__ int   g_cur[NN];
__device__ int   g_eid[ET];
__device__ float g_bnsum[2 * HID];
__device__ float g_bnscale[HID];
__device__ float g_bnshift[HID];
// bf16 split operand buffers
__device__ __nv_bfloat16 g_Ahi[(size_t)NN * INC];
__device__ __nv_bfloat16 g_Alo[(size_t)NN * INC];
__device__ __nv_bfloat16 g_Bhi[(size_t)FDIM * INC];   // transposed [n][k]
__device__ __nv_bfloat16 g_Blo[(size_t)FDIM * INC];

// ================= helpers =================
__device__ __forceinline__ uint32_t smem_u32(const void* p) {
    uint32_t a;
    asm("{ .reg .u64 t; cvta.to.shared.u64 t, %1; cvt.u32.u64 %0, t; }" : "=r"(a) : "l"(p));
    return a;
}

#define LDSM4(r0, r1, r2, r3, addr) \
    asm volatile("ldmatrix.sync.aligned.m8n8.x4.shared.b16 {%0,%1,%2,%3}, [%4];" \
        : "=r"(r0), "=r"(r1), "=r"(r2), "=r"(r3) : "r"(addr))

#define MMA_BF16(c, a0, a1, a2, a3, b0, b1) \
    asm volatile("mma.sync.aligned.m16n8k16.row.col.f32.bf16.bf16.f32 " \
        "{%0,%1,%2,%3}, {%4,%5,%6,%7}, {%8,%9}, {%0,%1,%2,%3};" \
        : "+f"((c)[0]), "+f"((c)[1]), "+f"((c)[2]), "+f"((c)[3]) \
        : "r"(a0), "r"(a1), "r"(a2), "r"(a3), "r"(b0), "r"(b1))

#define CPA(dst, src, sz) \
    asm volatile("cp.async.cg.shared.global [%0], [%1], 16, %2;" \
        :: "r"(dst), "l"(src), "r"(sz) : "memory")
#define CP_COMMIT() asm volatile("cp.async.commit_group;" ::: "memory")
#define CP_WAIT1()  asm volatile("cp.async.wait_group 1;" ::: "memory")
#define CP_WAIT0()  asm volatile("cp.async.wait_group 0;" ::: "memory")

// Split two fp32 into packed bf16x2 hi word + residual lo word.
__device__ __forceinline__ void pack2(float x0, float x1, uint32_t& hi, uint32_t& lo) {
    __nv_bfloat162 h = __floats2bfloat162_rn(x0, x1);
    uint32_t u = *reinterpret_cast<uint32_t*>(&h);
    float f0 = __uint_as_float(u << 16);
    float f1 = __uint_as_float(u & 0xffff0000u);
    __nv_bfloat162 l = __floats2bfloat162_rn(x0 - f0, x1 - f1);
    hi = u;
    lo = *reinterpret_cast<uint32_t*>(&l);
}

// ---------------- split kernels (fp32 -> bf16 hi/lo) ----------------
__global__ __launch_bounds__(256) void split_a_kernel(
    const float* __restrict__ A, int n4)
{
    int i = blockIdx.x * blockDim.x + threadIdx.x;
    if (i >= n4) return;
    float4 v = ((const float4*)A)[i];
    uint32_t h0, l0, h1, l1;
    pack2(v.x, v.y, h0, l0);
    pack2(v.z, v.w, h1, l1);
    ((uint2*)g_Ahi)[i] = make_uint2(h0, h1);
    ((uint2*)g_Alo)[i] = make_uint2(l0, l1);
}

// layer-2 A: fused BN(scale/shift) + ReLU + split.  h layout [n][256]
__global__ __launch_bounds__(256) void split_h_kernel(int n4)
{
    int i = blockIdx.x * blockDim.x + threadIdx.x;
    if (i >= n4) return;
    int c0 = (i & 63) * 4;
    float4 v = ((const float4*)g_h1)[i];
    v.x = fmaxf(v.x * g_bnscale[c0 + 0] + g_bnshift[c0 + 0], 0.f);
    v.y = fmaxf(v.y * g_bnscale[c0 + 1] + g_bnshift[c0 + 1], 0.f);
    v.z = fmaxf(v.z * g_bnscale[c0 + 2] + g_bnshift[c0 + 2], 0.f);
    v.w = fmaxf(v.w * g_bnscale[c0 + 3] + g_bnshift[c0 + 3], 0.f);
    uint32_t h0, l0, h1, l1;
    pack2(v.x, v.y, h0, l0);
    pack2(v.z, v.w, h1, l1);
    ((uint2*)g_Ahi)[i] = make_uint2(h0, h1);
    ((uint2*)g_Alo)[i] = make_uint2(l0, l1);
}

// W [K][1024] -> transposed split [1024][K].  block (32,8), grid (32, K/32)
__global__ __launch_bounds__(256) void split_w_kernel(
    const float* __restrict__ W, int K)
{
    __shared__ float tile[32][33];
    int nx = blockIdx.x * 32, ky = blockIdx.y * 32;
    int tx = threadIdx.x, ty = threadIdx.y;
#pragma unroll
    for (int j = 0; j < 32; j += 8)
        tile[ty + j][tx] = W[(size_t)(ky + ty + j) * FDIM + nx + tx];
    __syncthreads();
#pragma unroll
    for (int j = 0; j < 32; j += 8) {
        int n = nx + ty + j, k = ky + tx;
        float v = tile[tx][ty + j];
        __nv_bfloat16 h = __float2bfloat16(v);
        __nv_bfloat16 l = __float2bfloat16(v - __bfloat162float(h));
        g_Bhi[(size_t)n * K + k] = h;
        g_Blo[(size_t)n * K + k] = l;
    }
}

// ---------------- GEMM: C[M x 1024] = A[M x K] x B^T, bf16x3, cp.async ----
// SMEM per stage (65536B): Ahi@0 Alo@16384 Bhi@32768 Blo@49152; 2 stages.
// Row = 128B (64 bf16 K-chunk), XOR-swizzled 16B granules.
#define GEMM_SMEM_BYTES 131072

__device__ __forceinline__ void stage_cp(
    const __nv_bfloat16* __restrict__ Ah, const __nv_bfloat16* __restrict__ Al,
    const __nv_bfloat16* __restrict__ Bh, const __nv_bfloat16* __restrict__ Bl,
    int M, int K, int m0, int n0, int k0, uint32_t sbase)
{
    int t = threadIdx.x;
#pragma unroll
    for (int i = 0; i < 4; i++) {
        int g = i * 256 + t;            // 0..1023
        int row = g >> 3, col = g & 7;
        int gm = m0 + row;
        int ok = (gm < M) ? 16 : 0;
        size_t so = (size_t)(ok ? gm : 0) * K + k0 + col * 8;
        uint32_t off = (uint32_t)(row * 128 + ((col ^ (row & 7)) << 4));
        CPA(sbase + off, Ah + so, ok);
        CPA(sbase + 16384u + off, Al + so, ok);
    }
#pragma unroll
    for (int i = 0; i < 4; i++) {
        int g = i * 256 + t;
        int row = g >> 3, col = g & 7;
        size_t so = (size_t)(n0 + row) * K + k0 + col * 8;
        uint32_t off = (uint32_t)(row * 128 + ((col ^ (row & 7)) << 4));
        CPA(sbase + 32768u + off, Bh + so, 16);
        CPA(sbase + 49152u + off, Bl + so, 16);
    }
}

__global__ __launch_bounds__(256) void gemm_mma(
    const __nv_bfloat16* __restrict__ Ah, const __nv_bfloat16* __restrict__ Al,
    const __nv_bfloat16* __restrict__ Bh, const __nv_bfloat16* __restrict__ Bl,
    float* __restrict__ C, int M, int K)
{
    extern __shared__ char smem[];
    uint32_t sb = smem_u32(smem);
    int t = threadIdx.x, lane = t & 31, w = t >> 5;
    int m0 = blockIdx.y * 128, n0 = blockIdx.x * 128;
    int wm = (w & 1) * 64, wn = (w >> 1) * 32;

    int aRow = (lane & 7) | (((lane >> 3) & 1) << 3);
    int aG = (lane >> 4) & 1;
    int bRow = (lane & 7) | (((lane >> 4) & 1) << 3);
    int bG = (lane >> 3) & 1;

    float acc[4][4][4];
#pragma unroll
    for (int mi = 0; mi < 4; mi++)
#pragma unroll
        for (int ni = 0; ni < 4; ni++)
#pragma unroll
            for (int j = 0; j < 4; j++) acc[mi][ni][j] = 0.f;

    const int nst = K / 64;
    stage_cp(Ah, Al, Bh, Bl, M, K, m0, n0, 0, sb);
    CP_COMMIT();
    stage_cp(Ah, Al, Bh, Bl, M, K, m0, n0, 64, sb + 65536u);
    CP_COMMIT();

    for (int s = 0; s < nst; s++) {
        if (s == nst - 1) CP_WAIT0(); else CP_WAIT1();
        __syncthreads();
        uint32_t base = sb + (uint32_t)(s & 1) * 65536u;
#pragma unroll
        for (int ks = 0; ks < 4; ks++) {
            uint32_t bh[8], bl[8];
#pragma unroll
            for (int np = 0; np < 2; np++) {
                int rw = wn + np * 16 + bRow;
                uint32_t ad = base + 32768u + (uint32_t)(rw * 128 +
                              (((ks * 2 + bG) ^ (rw & 7)) << 4));
                LDSM4(bh[np * 4 + 0], bh[np * 4 + 1], bh[np * 4 + 2], bh[np * 4 + 3], ad);
                LDSM4(bl[np * 4 + 0], bl[np * 4 + 1], bl[np * 4 + 2], bl[np * 4 + 3], ad + 16384u);
            }
#pragma unroll
            for (int mi = 0; mi < 4; mi++) {
                int rw = wm + mi * 16 + aRow;
                uint32_t ad = base + (uint32_t)(rw * 128 +
                              (((ks * 2 + aG) ^ (rw & 7)) << 4));
                uint32_t ah0, ah1, ah2, ah3, al0, al1, al2, al3;
                LDSM4(ah0, ah1, ah2, ah3, ad);
                LDSM4(al0, al1, al2, al3, ad + 16384u);
#pragma unroll
                for (int ni = 0; ni < 4; ni++) {
                    MMA_BF16(acc[mi][ni], ah0, ah1, ah2, ah3, bh[ni * 2 + 0], bh[ni * 2 + 1]);
                    MMA_BF16(acc[mi][ni], ah0, ah1, ah2, ah3, bl[ni * 2 + 0], bl[ni * 2 + 1]);
                    MMA_BF16(acc[mi][ni], al0, al1, al2, al3, bh[ni * 2 + 0], bh[ni * 2 + 1]);
                }
            }
        }
        __syncthreads();
        if (s + 2 < nst) {
            stage_cp(Ah, Al, Bh, Bl, M, K, m0, n0, (s + 2) * 64, sb + (uint32_t)(s & 1) * 65536u);
            CP_COMMIT();
        }
    }

    // epilogue: direct register -> global stores
#pragma unroll
    for (int mi = 0; mi < 4; mi++) {
#pragma unroll
        for (int ni = 0; ni < 4; ni++) {
            int r = m0 + wm + mi * 16 + (lane >> 2);
            int c = n0 + wn + ni * 8 + (lane & 3) * 2;
            if (r < M)
                *(float2*)(C + (size_t)r * FDIM + c) = make_float2(acc[mi][ni][0], acc[mi][ni][1]);
            if (r + 8 < M)
                *(float2*)(C + (size_t)(r + 8) * FDIM + c) = make_float2(acc[mi][ni][2], acc[mi][ni][3]);
        }
    }
}

// ---------------- small utility kernels ----------------
__global__ void zero_kernel() {
    int i = blockIdx.x * blockDim.x + threadIdx.x;
    if (i < NN) g_cnt[i] = 0;
    if (i < 2 * HID) g_bnsum[i] = 0.f;
}

__global__ void hist_kernel(const int* __restrict__ ei) {
    int e = blockIdx.x * blockDim.x + threadIdx.x;
    if (e >= ET) return;
    int d = (e < EE) ? ei[EE + e] : (e - EE);
    atomicAdd(&g_cnt[d], 1);
}

__global__ void scan_kernel() {
    __shared__ int wsum[32];
    const int T = 1024;
    const int PER = (NN + T - 1) / T;
    int tid = threadIdx.x;
    int base = tid * PER;
    int loc[PER];
    int tot = 0;
#pragma unroll
    for (int i = 0; i < PER; i++) {
        int idx = base + i;
        int v = (idx < NN) ? g_cnt[idx] : 0;
        loc[i] = v; tot += v;
    }
    int lane = tid & 31, warp = tid >> 5;
    int x = tot;
#pragma unroll
    for (int o = 1; o < 32; o <<= 1) {
        int y = __shfl_up_sync(~0u, x, o);
        if (lane >= o) x += y;
    }
    if (lane == 31) wsum[warp] = x;
    __syncthreads();
    if (warp == 0) {
        int v = wsum[lane];
#pragma unroll
        for (int o = 1; o < 32; o <<= 1) {
            int y = __shfl_up_sync(~0u, v, o);
            if (lane >= o) v += y;
        }
        wsum[lane] = v;
    }
    __syncthreads();
    int excl = x - tot + ((warp > 0) ? wsum[warp - 1] : 0);
    int run = excl;
#pragma unroll
    for (int i = 0; i < PER; i++) {
        int idx = base + i;
        if (idx < NN) { g_off[idx] = run; g_cur[idx] = run; }
        run += loc[i];
    }
    if (tid == T - 1) g_off[NN] = run;
}

__global__ void scatter_kernel(const int* __restrict__ ei) {
    int e = blockIdx.x * blockDim.x + threadIdx.x;
    if (e >= ET) return;
    int d = (e < EE) ? ei[EE + e] : (e - EE);
    int pos = atomicAdd(&g_cur[d], 1);
    g_eid[pos] = e;
}

// ---------------- attention logits ----------------
__global__ __launch_bounds__(128) void sd_kernel(
    const float* __restrict__ xh, const float* __restrict__ a_src,
    const float* __restrict__ a_dst, float* __restrict__ s, float* __restrict__ d)
{
    int n = blockIdx.x;
    int w = threadIdx.x >> 5;
    int lane = threadIdx.x & 31;
    const float* row = xh + (size_t)n * FDIM + w * 256;
    const float* as = a_src + w * 256;
    const float* ad = a_dst + w * 256;
    float ss = 0.f, dd = 0.f;
#pragma unroll
    for (int c = lane; c < 256; c += 32) {
        float v = row[c];
        ss += v * as[c];
        dd += v * ad[c];
    }
#pragma unroll
    for (int o = 16; o; o >>= 1) {
        ss += __shfl_xor_sync(~0u, ss, o);
        dd += __shfl_xor_sync(~0u, dd, o);
    }
    if (lane == 0) { s[n * NH + w] = ss; d[n * NH + w] = dd; }
}

// ---------------- GAT aggregation: one block per dst node ----------------
__global__ __launch_bounds__(256) void gat_aggregate(
    const float* __restrict__ xh, const float* __restrict__ sarr,
    const float* __restrict__ darr, const int* __restrict__ ei,
    const float* __restrict__ bias, float* __restrict__ out)
{
    __shared__ float sh_max[NH], sh_rden[NH], sh_d[NH];
    __shared__ int   sh_src[64];
    __shared__ float sh_alpha[64 * NH];
    __shared__ float sh_acc[FDIM];

    int n = blockIdx.x;
    int t = threadIdx.x;
    int beg = g_off[n], end = g_off[n + 1];
    int deg = end - beg;

    if (t < 32) {
        int lane = t;
        float4 dd4 = *(const float4*)(darr + n * NH);
        float dh[NH] = {dd4.x, dd4.y, dd4.z, dd4.w};
        float mx[NH] = {-1e30f, -1e30f, -1e30f, -1e30f};
        for (int i = lane; i < deg; i += 32) {
            int e = g_eid[beg + i];
            int si = (e < EE) ? ei[e] : (e - EE);
            float4 sv = *(const float4*)(sarr + si * NH);
            float v;
            v = sv.x + dh[0]; v = v > 0.f ? v : 0.2f * v; mx[0] = fmaxf(mx[0], v);
            v = sv.y + dh[1]; v = v > 0.f ? v : 0.2f * v; mx[1] = fmaxf(mx[1], v);
            v = sv.z + dh[2]; v = v > 0.f ? v : 0.2f * v; mx[2] = fmaxf(mx[2], v);
            v = sv.w + dh[3]; v = v > 0.f ? v : 0.2f * v; mx[3] = fmaxf(mx[3], v);
        }
#pragma unroll
        for (int o = 16; o; o >>= 1)
#pragma unroll
            for (int h = 0; h < NH; h++)
                mx[h] = fmaxf(mx[h], __shfl_xor_sync(~0u, mx[h], o));
        float sm[NH] = {0.f, 0.f, 0.f, 0.f};
        for (int i = lane; i < deg; i += 32) {
            int e = g_eid[beg + i];
            int si = (e < EE) ? ei[e] : (e - EE);
            float4 sv = *(const float4*)(sarr + si * NH);
            float v;
            v = sv.x + dh[0]; v = v > 0.f ? v : 0.2f * v; sm[0] += expf(v - mx[0]);
            v = sv.y + dh[1]; v = v > 0.f ? v : 0.2f * v; sm[1] += expf(v - mx[1]);
            v = sv.z + dh[2]; v = v > 0.f ? v : 0.2f * v; sm[2] += expf(v - mx[2]);
            v = sv.w + dh[3]; v = v > 0.f ? v : 0.2f * v; sm[3] += expf(v - mx[3]);
        }
#pragma unroll
        for (int o = 16; o; o >>= 1)
#pragma unroll
            for (int h = 0; h < NH; h++)
                sm[h] += __shfl_xor_sync(~0u, sm[h], o);
        if (lane == 0) {
#pragma unroll
            for (int h = 0; h < NH; h++) {
                sh_max[h] = mx[h];
                sh_rden[h] = 1.f / sm[h];
                sh_d[h] = dh[h];
            }
        }
    }
    __syncthreads();

    float a0 = 0.f, a1 = 0.f, a2 = 0.f, a3 = 0.f;
    int hh = t >> 6;

    for (int c0 = 0; c0 < deg; c0 += 64) {
        int cn = min(64, deg - c0);
        int te = t >> 2, th = t & 3;
        if (te < cn) {
            int e = g_eid[beg + c0 + te];
            int si = (e < EE) ? ei[e] : (e - EE);
            if (th == 0) sh_src[te] = si;
            float v = sarr[si * NH + th] + sh_d[th];
            v = v > 0.f ? v : 0.2f * v;
            sh_alpha[te * NH + th] = expf(v - sh_max[th]) * sh_rden[th];
        }
        __syncthreads();
        for (int j = 0; j < cn; j++) {
            int si = sh_src[j];
            float al = sh_alpha[j * NH + hh];
            float4 xv = *(const float4*)(xh + (size_t)si * FDIM + t * 4);
            a0 += al * xv.x; a1 += al * xv.y; a2 += al * xv.z; a3 += al * xv.w;
        }
        __syncthreads();
    }

    sh_acc[t * 4 + 0] = a0;
    sh_acc[t * 4 + 1] = a1;
    sh_acc[t * 4 + 2] = a2;
    sh_acc[t * 4 + 3] = a3;
    __syncthreads();
    float r = 0.25f * (sh_acc[t] + sh_acc[256 + t] + sh_acc[512 + t] + sh_acc[768 + t]) + bias[t];
    out[(size_t)n * 256 + t] = r;
}

// ---------------- BatchNorm stats ----------------
__global__ __launch_bounds__(256) void bn_partial() {
    int t = threadIdx.x;
    float sum = 0.f, sq = 0.f;
    for (int n = blockIdx.x; n < NN; n += gridDim.x) {
        float v = g_h1[(size_t)n * HID + t];
        sum += v; sq += v * v;
    }
    atomicAdd(&g_bnsum[t], sum);
    atomicAdd(&g_bnsum[HID + t], sq);
}

__global__ __launch_bounds__(256) void bn_finalize(
    const float* __restrict__ gamma, const float* __restrict__ beta)
{
    int t = threadIdx.x;
    float mu = g_bnsum[t] / (float)NN;
    float var = g_bnsum[HID + t] / (float)NN - mu * mu;
    float sc = gamma[t] * rsqrtf(var + EPS);
    g_bnscale[t] = sc;
    g_bnshift[t] = beta[t] - mu * sc;
}

// ---------------- launch ----------------
extern "C" void kernel_launch(void* const* d_in, const int* in_sizes, int n_in,
                              void* d_out, int out_size)
{
    const float* x     = (const float*)d_in[0];
    const int*   ei    = (const int*)d_in[1];
    const float* W1    = (const float*)d_in[2];
    const float* as1   = (const float*)d_in[3];
    const float* ad1   = (const float*)d_in[4];
    const float* b1    = (const float*)d_in[5];
    const float* gamma = (const float*)d_in[6];
    const float* beta  = (const float*)d_in[7];
    const float* W2    = (const float*)d_in[8];
    const float* as2   = (const float*)d_in[9];
    const float* ad2   = (const float*)d_in[10];
    const float* b2    = (const float*)d_in[11];
    float* out         = (float*)d_out;

    float* xh1; cudaGetSymbolAddress((void**)&xh1, g_xh1);
    float* xh2; cudaGetSymbolAddress((void**)&xh2, g_xh2);
    float* h1;  cudaGetSymbolAddress((void**)&h1,  g_h1);
    float* s1;  cudaGetSymbolAddress((void**)&s1,  g_s1);
    float* d1;  cudaGetSymbolAddress((void**)&d1,  g_d1);
    float* s2;  cudaGetSymbolAddress((void**)&s2,  g_s2);
    float* d2;  cudaGetSymbolAddress((void**)&d2,  g_d2);
    __nv_bfloat16* Ahi; cudaGetSymbolAddress((void**)&Ahi, g_Ahi);
    __nv_bfloat16* Alo; cudaGetSymbolAddress((void**)&Alo, g_Alo);
    __nv_bfloat16* Bhi; cudaGetSymbolAddress((void**)&Bhi, g_Bhi);
    __nv_bfloat16* Blo; cudaGetSymbolAddress((void**)&Blo, g_Blo);

    static bool inited = false;
    static cudaStream_t s2str;
    static cudaEvent_t evFork, evJoin;
    if (!inited) {
        cudaStreamCreateWithFlags(&s2str, cudaStreamNonBlocking);
        cudaEventCreateWithFlags(&evFork, cudaEventDisableTiming);
        cudaEventCreateWithFlags(&evJoin, cudaEventDisableTiming);
        cudaFuncSetAttribute(gemm_mma, cudaFuncAttributeMaxDynamicSharedMemorySize,
                             GEMM_SMEM_BYTES);
        inited = true;
    }

    // ---- fork: CSR build on side stream, overlapped with GEMM1 chain ----
    cudaEventRecord(evFork, 0);
    cudaStreamWaitEvent(s2str, evFork, 0);
    zero_kernel<<<(NN + 255) / 256, 256, 0, s2str>>>();
    hist_kernel<<<(ET + 255) / 256, 256, 0, s2str>>>(ei);
    scan_kernel<<<1, 1024, 0, s2str>>>();
    scatter_kernel<<<(ET + 255) / 256, 256, 0, s2str>>>(ei);
    cudaEventRecord(evJoin, s2str);

    dim3 ggrid(FDIM / 128, (NN + 127) / 128);

    // ---- Layer 1 ----
    split_a_kernel<<<(NN * INC / 4 + 255) / 256, 256>>>(x, NN * INC / 4);
    split_w_kernel<<<dim3(FDIM / 32, INC / 32), dim3(32, 8)>>>(W1, INC);
    gemm_mma<<<ggrid, 256, GEMM_SMEM_BYTES>>>(Ahi, Alo, Bhi, Blo, xh1, NN, INC);
    sd_kernel<<<NN, 128>>>(xh1, as1, ad1, s1, d1);
    cudaStreamWaitEvent(0, evJoin, 0);   // CSR ready before aggregation
    gat_aggregate<<<NN, 256>>>(xh1, s1, d1, ei, b1, h1);

    // ---- BN stats + fused (bn+relu+split) into layer-2 A operand ----
    bn_partial<<<296, 256>>>();
    bn_finalize<<<1, 256>>>(gamma, beta);
    split_h_kernel<<<(NN * HID / 4 + 255) / 256, 256>>>(NN * HID / 4);
    split_w_kernel<<<dim3(FDIM / 32, HID / 32), dim3(32, 8)>>>(W2, HID);

    // ---- Layer 2 ----
    gemm_mma<<<ggrid, 256, GEMM_SMEM_BYTES>>>(Ahi, Alo, Bhi, Blo, xh2, NN, HID);
    sd_kernel<<<NN, 128>>>(xh2, as2, ad2, s2, d2);
    gat_aggregate<<<NN, 256>>>(xh2, s2, d2, ei, b2, out);
}

// round 6
// speedup vs baseline: 2.2291x; 1.0134x over previous
#include <cuda_runtime.h>
#include <cuda_bf16.h>
#include <cstdint>
#include <math.h>

// Problem constants
#define NN   10000          // nodes
#define EE   160000         // edges (before self loops)
#define ET   (EE + NN)      // edges + self loops
#define INC  768
#define HID  256
#define NH   4
#define FDIM 1024           // NH*HID == NH*OUTC
#define EPS  1e-5f

// ---------------- device scratch (no allocations allowed) ----------------
__device__ float g_xh1[(size_t)NN * FDIM];   // 41 MB
__device__ float g_xh2[(size_t)NN * FDIM];   // 41 MB
__device__ float g_h1[(size_t)NN * HID];     // 10 MB
__device__ float g_s1[NN * NH];
__device__ float g_d1[NN * NH];
__device__ float g_s2[NN * NH];
__device__ float g_d2[NN * NH];
__device__ int   g_cnt[NN];
__device__ int   g_off[NN + 1];
__device__ int   g_cur[NN];
__device__ int   g_eid[ET];
__device__ float g_bnsum[2 * HID];
__device__ float g_bnscale[HID];
__device__ float g_bnshift[HID];
// bf16 split operand buffers
__device__ __nv_bfloat16 g_Ahi[(size_t)NN * INC];
__device__ __nv_bfloat16 g_Alo[(size_t)NN * INC];
__device__ __nv_bfloat16 g_Bhi[(size_t)FDIM * INC];    // W1^T split [1024][768]
__device__ __nv_bfloat16 g_Blo[(size_t)FDIM * INC];
__device__ __nv_bfloat16 g_B2hi[(size_t)FDIM * HID];   // W2^T split [1024][256]
__device__ __nv_bfloat16 g_B2lo[(size_t)FDIM * HID];

// ================= helpers =================
__device__ __forceinline__ uint32_t smem_u32(const void* p) {
    uint32_t a;
    asm("{ .reg .u64 t; cvta.to.shared.u64 t, %1; cvt.u32.u64 %0, t; }" : "=r"(a) : "l"(p));
    return a;
}

#define LDSM4(r0, r1, r2, r3, addr) \
    asm volatile("ldmatrix.sync.aligned.m8n8.x4.shared.b16 {%0,%1,%2,%3}, [%4];" \
        : "=r"(r0), "=r"(r1), "=r"(r2), "=r"(r3) : "r"(addr))

#define MMA_BF16(c, a0, a1, a2, a3, b0, b1) \
    asm volatile("mma.sync.aligned.m16n8k16.row.col.f32.bf16.bf16.f32 " \
        "{%0,%1,%2,%3}, {%4,%5,%6,%7}, {%8,%9}, {%0,%1,%2,%3};" \
        : "+f"((c)[0]), "+f"((c)[1]), "+f"((c)[2]), "+f"((c)[3]) \
        : "r"(a0), "r"(a1), "r"(a2), "r"(a3), "r"(b0), "r"(b1))

#define CPA(dst, src, sz) \
    asm volatile("cp.async.cg.shared.global [%0], [%1], 16, %2;" \
        :: "r"(dst), "l"(src), "r"(sz) : "memory")
#define CP_COMMIT() asm volatile("cp.async.commit_group;" ::: "memory")
#define CP_WAIT1()  asm volatile("cp.async.wait_group 1;" ::: "memory")
#define CP_WAIT0()  asm volatile("cp.async.wait_group 0;" ::: "memory")

// Split two fp32 into packed bf16x2 hi word + residual lo word.
__device__ __forceinline__ void pack2(float x0, float x1, uint32_t& hi, uint32_t& lo) {
    __nv_bfloat162 h = __floats2bfloat162_rn(x0, x1);
    uint32_t u = *reinterpret_cast<uint32_t*>(&h);
    float f0 = __uint_as_float(u << 16);
    float f1 = __uint_as_float(u & 0xffff0000u);
    __nv_bfloat162 l = __floats2bfloat162_rn(x0 - f0, x1 - f1);
    hi = u;
    lo = *reinterpret_cast<uint32_t*>(&l);
}

// ---------------- split kernels (fp32 -> bf16 hi/lo) ----------------
__global__ __launch_bounds__(256) void split_a_kernel(
    const float* __restrict__ A, int n4)
{
    int i = blockIdx.x * blockDim.x + threadIdx.x;
    if (i >= n4) return;
    float4 v = ((const float4*)A)[i];
    uint32_t h0, l0, h1, l1;
    pack2(v.x, v.y, h0, l0);
    pack2(v.z, v.w, h1, l1);
    ((uint2*)g_Ahi)[i] = make_uint2(h0, h1);
    ((uint2*)g_Alo)[i] = make_uint2(l0, l1);
}

// layer-2 A: fused BN(scale/shift) + ReLU + split.  h layout [n][256]
__global__ __launch_bounds__(256) void split_h_kernel(int n4)
{
    int i = blockIdx.x * blockDim.x + threadIdx.x;
    if (i >= n4) return;
    int c0 = (i & 63) * 4;
    float4 v = ((const float4*)g_h1)[i];
    v.x = fmaxf(v.x * g_bnscale[c0 + 0] + g_bnshift[c0 + 0], 0.f);
    v.y = fmaxf(v.y * g_bnscale[c0 + 1] + g_bnshift[c0 + 1], 0.f);
    v.z = fmaxf(v.z * g_bnscale[c0 + 2] + g_bnshift[c0 + 2], 0.f);
    v.w = fmaxf(v.w * g_bnscale[c0 + 3] + g_bnshift[c0 + 3], 0.f);
    uint32_t h0, l0, h1, l1;
    pack2(v.x, v.y, h0, l0);
    pack2(v.z, v.w, h1, l1);
    ((uint2*)g_Ahi)[i] = make_uint2(h0, h1);
    ((uint2*)g_Alo)[i] = make_uint2(l0, l1);
}

// W [K][1024] -> transposed split [1024][K].  block (32,8), grid (32, K/32)
__global__ __launch_bounds__(256) void split_w_kernel(
    const float* __restrict__ W, __nv_bfloat16* __restrict__ Bh,
    __nv_bfloat16* __restrict__ Bl, int K)
{
    __shared__ float tile[32][33];
    int nx = blockIdx.x * 32, ky = blockIdx.y * 32;
    int tx = threadIdx.x, ty = threadIdx.y;
#pragma unroll
    for (int j = 0; j < 32; j += 8)
        tile[ty + j][tx] = W[(size_t)(ky + ty + j) * FDIM + nx + tx];
    __syncthreads();
#pragma unroll
    for (int j = 0; j < 32; j += 8) {
        int n = nx + ty + j, k = ky + tx;
        float v = tile[tx][ty + j];
        __nv_bfloat16 h = __float2bfloat16(v);
        __nv_bfloat16 l = __float2bfloat16(v - __bfloat162float(h));
        Bh[(size_t)n * K + k] = h;
        Bl[(size_t)n * K + k] = l;
    }
}

// ---------------- GEMM: C[M x 1024] = A[M x K] x B^T, bf16x3, cp.async ----
// K-chunk 32: stage = Ahi(8K) Alo(8K) Bhi(8K) Blo(8K) = 32KB; double buffer.
// Rows of 64B (32 bf16), swizzle: granule ^= (row>>1)&3.
#define GEMM_SMEM_BYTES 65536

__device__ __forceinline__ void stage_cp(
    const __nv_bfloat16* __restrict__ Ah, const __nv_bfloat16* __restrict__ Al,
    const __nv_bfloat16* __restrict__ Bh, const __nv_bfloat16* __restrict__ Bl,
    int M, int K, int m0, int n0, int k0, uint32_t sbase)
{
    int t = threadIdx.x;
#pragma unroll
    for (int i = 0; i < 2; i++) {
        int g = i * 256 + t;            // 0..511
        int row = g >> 2, gr = g & 3;
        uint32_t off = (uint32_t)(row * 64 + (((gr ^ ((row >> 1) & 3))) << 4));
        int gm = m0 + row;
        int ok = (gm < M) ? 16 : 0;
        size_t so = (size_t)(ok ? gm : 0) * K + k0 + gr * 8;
        CPA(sbase + off, Ah + so, ok);
        CPA(sbase + 8192u + off, Al + so, ok);
        size_t sbo = (size_t)(n0 + row) * K + k0 + gr * 8;
        CPA(sbase + 16384u + off, Bh + sbo, 16);
        CPA(sbase + 24576u + off, Bl + sbo, 16);
    }
}

__global__ __launch_bounds__(256, 2) void gemm_mma(
    const __nv_bfloat16* __restrict__ Ah, const __nv_bfloat16* __restrict__ Al,
    const __nv_bfloat16* __restrict__ Bh, const __nv_bfloat16* __restrict__ Bl,
    float* __restrict__ C, float* __restrict__ sarr, float* __restrict__ darr,
    const float* __restrict__ a_src, const float* __restrict__ a_dst,
    int M, int K)
{
    extern __shared__ char smem[];
    uint32_t sb = smem_u32(smem);
    int t = threadIdx.x, lane = t & 31, w = t >> 5;
    int m0 = blockIdx.y * 128, n0 = blockIdx.x * 128;
    int wm = (w & 1) * 64, wn = (w >> 1) * 32;

    int aRow = lane & 15;          // lanes 0-15 rows, 16-31 second granule
    int aG = (lane >> 4) & 1;
    int bRow = (lane & 7) | (((lane >> 4) & 1) << 3);
    int bG = (lane >> 3) & 1;

    float acc[4][4][4];
#pragma unroll
    for (int mi = 0; mi < 4; mi++)
#pragma unroll
        for (int ni = 0; ni < 4; ni++)
#pragma unroll
            for (int j = 0; j < 4; j++) acc[mi][ni][j] = 0.f;

    const int nst = K / 32;
    stage_cp(Ah, Al, Bh, Bl, M, K, m0, n0, 0, sb);
    CP_COMMIT();
    stage_cp(Ah, Al, Bh, Bl, M, K, m0, n0, 32, sb + 32768u);
    CP_COMMIT();

    for (int s = 0; s < nst; s++) {
        if (s == nst - 1) CP_WAIT0(); else CP_WAIT1();
        __syncthreads();
        uint32_t base = sb + (uint32_t)(s & 1) * 32768u;
#pragma unroll
        for (int ks = 0; ks < 2; ks++) {
            uint32_t bh[8], bl[8];
#pragma unroll
            for (int np = 0; np < 2; np++) {
                int rw = wn + np * 16 + bRow;
                int g = ks * 2 + bG;
                uint32_t ad = base + 16384u + (uint32_t)(rw * 64 +
                              ((g ^ ((rw >> 1) & 3)) << 4));
                LDSM4(bh[np * 4 + 0], bh[np * 4 + 1], bh[np * 4 + 2], bh[np * 4 + 3], ad);
                LDSM4(bl[np * 4 + 0], bl[np * 4 + 1], bl[np * 4 + 2], bl[np * 4 + 3], ad + 8192u);
            }
#pragma unroll
            for (int mi = 0; mi < 4; mi++) {
                int rw = wm + mi * 16 + aRow;
                int g = ks * 2 + aG;
                uint32_t ad = base + (uint32_t)(rw * 64 +
                              ((g ^ ((rw >> 1) & 3)) << 4));
                uint32_t ah0, ah1, ah2, ah3, al0, al1, al2, al3;
                LDSM4(ah0, ah1, ah2, ah3, ad);
                LDSM4(al0, al1, al2, al3, ad + 8192u);
#pragma unroll
                for (int ni = 0; ni < 4; ni++) {
                    MMA_BF16(acc[mi][ni], ah0, ah1, ah2, ah3, bh[ni * 2 + 0], bh[ni * 2 + 1]);
                    MMA_BF16(acc[mi][ni], ah0, ah1, ah2, ah3, bl[ni * 2 + 0], bl[ni * 2 + 1]);
                    MMA_BF16(acc[mi][ni], al0, al1, al2, al3, bh[ni * 2 + 0], bh[ni * 2 + 1]);
                }
            }
        }
        __syncthreads();
        if (s + 2 < nst) {
            stage_cp(Ah, Al, Bh, Bl, M, K, m0, n0, (s + 2) * 32, sb + (uint32_t)(s & 1) * 32768u);
            CP_COMMIT();
        }
    }

    // ---- epilogue 1: C stores ----
#pragma unroll
    for (int mi = 0; mi < 4; mi++) {
#pragma unroll
        for (int ni = 0; ni < 4; ni++) {
            int r = m0 + wm + mi * 16 + (lane >> 2);
            int c = n0 + wn + ni * 8 + (lane & 3) * 2;
            if (r < M)
                *(float2*)(C + (size_t)r * FDIM + c) = make_float2(acc[mi][ni][0], acc[mi][ni][1]);
            if (r + 8 < M)
                *(float2*)(C + (size_t)(r + 8) * FDIM + c) = make_float2(acc[mi][ni][2], acc[mi][ni][3]);
        }
    }

    // ---- epilogue 2: fused attention-logit partial dots (s, d) ----
    float as0[4], as1[4], ad0[4], ad1[4];
#pragma unroll
    for (int ni = 0; ni < 4; ni++) {
        int gc = n0 + wn + ni * 8 + (lane & 3) * 2;
        as0[ni] = a_src[gc];  as1[ni] = a_src[gc + 1];
        ad0[ni] = a_dst[gc];  ad1[ni] = a_dst[gc + 1];
    }
    int h = (n0 + wn) >> 8;
#pragma unroll
    for (int mi = 0; mi < 4; mi++) {
        float s0 = 0.f, d0 = 0.f, s1 = 0.f, d1 = 0.f;
#pragma unroll
        for (int ni = 0; ni < 4; ni++) {
            s0 += acc[mi][ni][0] * as0[ni] + acc[mi][ni][1] * as1[ni];
            d0 += acc[mi][ni][0] * ad0[ni] + acc[mi][ni][1] * ad1[ni];
            s1 += acc[mi][ni][2] * as0[ni] + acc[mi][ni][3] * as1[ni];
            d1 += acc[mi][ni][2] * ad0[ni] + acc[mi][ni][3] * ad1[ni];
        }
#pragma unroll
        for (int o = 1; o <= 2; o <<= 1) {
            s0 += __shfl_xor_sync(~0u, s0, o);
            d0 += __shfl_xor_sync(~0u, d0, o);
            s1 += __shfl_xor_sync(~0u, s1, o);
            d1 += __shfl_xor_sync(~0u, d1, o);
        }
        if ((lane & 3) == 0) {
            int r = m0 + wm + mi * 16 + (lane >> 2);
            if (r < M) {
                atomicAdd(&sarr[r * NH + h], s0);
                atomicAdd(&darr[r * NH + h], d0);
            }
            if (r + 8 < M) {
                atomicAdd(&sarr[(r + 8) * NH + h], s1);
                atomicAdd(&darr[(r + 8) * NH + h], d1);
            }
        }
    }
}

// ---------------- small utility kernels ----------------
__global__ void zero_csr_kernel() {
    int i = blockIdx.x * blockDim.x + threadIdx.x;
    if (i < NN) g_cnt[i] = 0;
}

__global__ void zero_sd_kernel() {
    int i = blockIdx.x * blockDim.x + threadIdx.x;
    if (i < NN * NH) {
        g_s1[i] = 0.f; g_d1[i] = 0.f;
        g_s2[i] = 0.f; g_d2[i] = 0.f;
    }
    if (i < 2 * HID) g_bnsum[i] = 0.f;
}

__global__ void hist_kernel(const int* __restrict__ ei) {
    int e = blockIdx.x * blockDim.x + threadIdx.x;
    if (e >= ET) return;
    int d = (e < EE) ? ei[EE + e] : (e - EE);
    atomicAdd(&g_cnt[d], 1);
}

__global__ void scan_kernel() {
    __shared__ int wsum[32];
    const int T = 1024;
    const int PER = (NN + T - 1) / T;
    int tid = threadIdx.x;
    int base = tid * PER;
    int loc[PER];
    int tot = 0;
#pragma unroll
    for (int i = 0; i < PER; i++) {
        int idx = base + i;
        int v = (idx < NN) ? g_cnt[idx] : 0;
        loc[i] = v; tot += v;
    }
    int lane = tid & 31, warp = tid >> 5;
    int x = tot;
#pragma unroll
    for (int o = 1; o < 32; o <<= 1) {
        int y = __shfl_up_sync(~0u, x, o);
        if (lane >= o) x += y;
    }
    if (lane == 31) wsum[warp] = x;
    __syncthreads();
    if (warp == 0) {
        int v = wsum[lane];
#pragma unroll
        for (int o = 1; o < 32; o <<= 1) {
            int y = __shfl_up_sync(~0u, v, o);
            if (lane >= o) v += y;
        }
        wsum[lane] = v;
    }
    __syncthreads();
    int excl = x - tot + ((warp > 0) ? wsum[warp - 1] : 0);
    int run = excl;
#pragma unroll
    for (int i = 0; i < PER; i++) {
        int idx = base + i;
        if (idx < NN) { g_off[idx] = run; g_cur[idx] = run; }
        run += loc[i];
    }
    if (tid == T - 1) g_off[NN] = run;
}

__global__ void scatter_kernel(const int* __restrict__ ei) {
    int e = blockIdx.x * blockDim.x + threadIdx.x;
    if (e >= ET) return;
    int d = (e < EE) ? ei[EE + e] : (e - EE);
    int pos = atomicAdd(&g_cur[d], 1);
    g_eid[pos] = e;
}

// ---------------- GAT aggregation: one block per dst node ----------------
__global__ __launch_bounds__(256) void gat_aggregate(
    const float* __restrict__ xh, const float* __restrict__ sarr,
    const float* __restrict__ darr, const int* __restrict__ ei,
    const float* __restrict__ bias, float* __restrict__ out)
{
    __shared__ float sh_max[NH], sh_rden[NH], sh_d[NH];
    __shared__ int   sh_src[64];
    __shared__ float sh_alpha[64 * NH];
    __shared__ float sh_acc[FDIM];

    int n = blockIdx.x;
    int t = threadIdx.x;
    int beg = g_off[n], end = g_off[n + 1];
    int deg = end - beg;

    if (t < 32) {
        int lane = t;
        float4 dd4 = *(const float4*)(darr + n * NH);
        float dh[NH] = {dd4.x, dd4.y, dd4.z, dd4.w};
        float mx[NH] = {-1e30f, -1e30f, -1e30f, -1e30f};
        for (int i = lane; i < deg; i += 32) {
            int e = g_eid[beg + i];
            int si = (e < EE) ? ei[e] : (e - EE);
            float4 sv = *(const float4*)(sarr + si * NH);
            float v;
            v = sv.x + dh[0]; v = v > 0.f ? v : 0.2f * v; mx[0] = fmaxf(mx[0], v);
            v = sv.y + dh[1]; v = v > 0.f ? v : 0.2f * v; mx[1] = fmaxf(mx[1], v);
            v = sv.z + dh[2]; v = v > 0.f ? v : 0.2f * v; mx[2] = fmaxf(mx[2], v);
            v = sv.w + dh[3]; v = v > 0.f ? v : 0.2f * v; mx[3] = fmaxf(mx[3], v);
        }
#pragma unroll
        for (int o = 16; o; o >>= 1)
#pragma unroll
            for (int h = 0; h < NH; h++)
                mx[h] = fmaxf(mx[h], __shfl_xor_sync(~0u, mx[h], o));
        float sm[NH] = {0.f, 0.f, 0.f, 0.f};
        for (int i = lane; i < deg; i += 32) {
            int e = g_eid[beg + i];
            int si = (e < EE) ? ei[e] : (e - EE);
            float4 sv = *(const float4*)(sarr + si * NH);
            float v;
            v = sv.x + dh[0]; v = v > 0.f ? v : 0.2f * v; sm[0] += expf(v - mx[0]);
            v = sv.y + dh[1]; v = v > 0.f ? v : 0.2f * v; sm[1] += expf(v - mx[1]);
            v = sv.z + dh[2]; v = v > 0.f ? v : 0.2f * v; sm[2] += expf(v - mx[2]);
            v = sv.w + dh[3]; v = v > 0.f ? v : 0.2f * v; sm[3] += expf(v - mx[3]);
        }
#pragma unroll
        for (int o = 16; o; o >>= 1)
#pragma unroll
            for (int h = 0; h < NH; h++)
                sm[h] += __shfl_xor_sync(~0u, sm[h], o);
        if (lane == 0) {
#pragma unroll
            for (int h = 0; h < NH; h++) {
                sh_max[h] = mx[h];
                sh_rden[h] = 1.f / sm[h];
                sh_d[h] = dh[h];
            }
        }
    }
    __syncthreads();

    float a0 = 0.f, a1 = 0.f, a2 = 0.f, a3 = 0.f;
    int hh = t >> 6;
    const float* xbase = xh + t * 4;

    for (int c0 = 0; c0 < deg; c0 += 64) {
        int cn = min(64, deg - c0);
        int te = t >> 2, th = t & 3;
        if (te < cn) {
            int e = g_eid[beg + c0 + te];
            int si = (e < EE) ? ei[e] : (e - EE);
            if (th == 0) sh_src[te] = si;
            float v = sarr[si * NH + th] + sh_d[th];
            v = v > 0.f ? v : 0.2f * v;
            sh_alpha[te * NH + th] = expf(v - sh_max[th]) * sh_rden[th];
        }
        __syncthreads();
        int j = 0;
        for (; j + 2 <= cn; j += 2) {
            int si0 = sh_src[j], si1 = sh_src[j + 1];
            float al0 = sh_alpha[j * NH + hh], al1 = sh_alpha[(j + 1) * NH + hh];
            float4 x0 = *(const float4*)(xbase + (size_t)si0 * FDIM);
            float4 x1 = *(const float4*)(xbase + (size_t)si1 * FDIM);
            a0 += al0 * x0.x + al1 * x1.x;
            a1 += al0 * x0.y + al1 * x1.y;
            a2 += al0 * x0.z + al1 * x1.z;
            a3 += al0 * x0.w + al1 * x1.w;
        }
        if (j < cn) {
            int si0 = sh_src[j];
            float al0 = sh_alpha[j * NH + hh];
            float4 x0 = *(const float4*)(xbase + (size_t)si0 * FDIM);
            a0 += al0 * x0.x; a1 += al0 * x0.y; a2 += al0 * x0.z; a3 += al0 * x0.w;
        }
        __syncthreads();
    }

    sh_acc[t * 4 + 0] = a0;
    sh_acc[t * 4 + 1] = a1;
    sh_acc[t * 4 + 2] = a2;
    sh_acc[t * 4 + 3] = a3;
    __syncthreads();
    float r = 0.25f * (sh_acc[t] + sh_acc[256 + t] + sh_acc[512 + t] + sh_acc[768 + t]) + bias[t];
    out[(size_t)n * 256 + t] = r;
}

// ---------------- BatchNorm stats ----------------
__global__ __launch_bounds__(256) void bn_partial() {
    int t = threadIdx.x;
    float sum = 0.f, sq = 0.f;
    for (int n = blockIdx.x; n < NN; n += gridDim.x) {
        float v = g_h1[(size_t)n * HID + t];
        sum += v; sq += v * v;
    }
    atomicAdd(&g_bnsum[t], sum);
    atomicAdd(&g_bnsum[HID + t], sq);
}

__global__ __launch_bounds__(256) void bn_finalize(
    const float* __restrict__ gamma, const float* __restrict__ beta)
{
    int t = threadIdx.x;
    float mu = g_bnsum[t] / (float)NN;
    float var = g_bnsum[HID + t] / (float)NN - mu * mu;
    float sc = gamma[t] * rsqrtf(var + EPS);
    g_bnscale[t] = sc;
    g_bnshift[t] = beta[t] - mu * sc;
}

// ---------------- launch ----------------
extern "C" void kernel_launch(void* const* d_in, const int* in_sizes, int n_in,
                              void* d_out, int out_size)
{
    const float* x     = (const float*)d_in[0];
    const int*   ei    = (const int*)d_in[1];
    const float* W1    = (const float*)d_in[2];
    const float* as1   = (const float*)d_in[3];
    const float* ad1   = (const float*)d_in[4];
    const float* b1    = (const float*)d_in[5];
    const float* gamma = (const float*)d_in[6];
    const float* beta  = (const float*)d_in[7];
    const float* W2    = (const float*)d_in[8];
    const float* as2   = (const float*)d_in[9];
    const float* ad2   = (const float*)d_in[10];
    const float* b2    = (const float*)d_in[11];
    float* out         = (float*)d_out;

    float* xh1; cudaGetSymbolAddress((void**)&xh1, g_xh1);
    float* xh2; cudaGetSymbolAddress((void**)&xh2, g_xh2);
    float* h1;  cudaGetSymbolAddress((void**)&h1,  g_h1);
    float* s1;  cudaGetSymbolAddress((void**)&s1,  g_s1);
    float* d1;  cudaGetSymbolAddress((void**)&d1,  g_d1);
    float* s2;  cudaGetSymbolAddress((void**)&s2,  g_s2);
    float* d2;  cudaGetSymbolAddress((void**)&d2,  g_d2);
    __nv_bfloat16* Ahi; cudaGetSymbolAddress((void**)&Ahi, g_Ahi);
    __nv_bfloat16* Alo; cudaGetSymbolAddress((void**)&Alo, g_Alo);
    __nv_bfloat16* Bhi; cudaGetSymbolAddress((void**)&Bhi, g_Bhi);
    __nv_bfloat16* Blo; cudaGetSymbolAddress((void**)&Blo, g_Blo);
    __nv_bfloat16* B2hi; cudaGetSymbolAddress((void**)&B2hi, g_B2hi);
    __nv_bfloat16* B2lo; cudaGetSymbolAddress((void**)&B2lo, g_B2lo);

    static bool inited = false;
    static cudaStream_t s2str;
    static cudaEvent_t evFork, evJoin;
    if (!inited) {
        cudaStreamCreateWithFlags(&s2str, cudaStreamNonBlocking);
        cudaEventCreateWithFlags(&evFork, cudaEventDisableTiming);
        cudaEventCreateWithFlags(&evJoin, cudaEventDisableTiming);
        cudaFuncSetAttribute(gemm_mma, cudaFuncAttributeMaxDynamicSharedMemorySize,
                             GEMM_SMEM_BYTES);
        inited = true;
    }

    // ---- fork: CSR build on side stream, overlapped with GEMM1 chain ----
    cudaEventRecord(evFork, 0);
    cudaStreamWaitEvent(s2str, evFork, 0);
    zero_csr_kernel<<<(NN + 255) / 256, 256, 0, s2str>>>();
    hist_kernel<<<(ET + 255) / 256, 256, 0, s2str>>>(ei);
    scan_kernel<<<1, 1024, 0, s2str>>>();
    scatter_kernel<<<(ET + 255) / 256, 256, 0, s2str>>>(ei);
    cudaEventRecord(evJoin, s2str);

    dim3 ggrid(FDIM / 128, (NN + 127) / 128);

    // ---- main stream: zero s/d, splits (both W up front) ----
    zero_sd_kernel<<<(NN * NH + 255) / 256, 256>>>();
    split_a_kernel<<<(NN * INC / 4 + 255) / 256, 256>>>(x, NN * INC / 4);
    split_w_kernel<<<dim3(FDIM / 32, INC / 32), dim3(32, 8)>>>(W1, Bhi, Blo, INC);
    split_w_kernel<<<dim3(FDIM / 32, HID / 32), dim3(32, 8)>>>(W2, B2hi, B2lo, HID);

    // ---- Layer 1: GEMM with fused s/d epilogue ----
    gemm_mma<<<ggrid, 256, GEMM_SMEM_BYTES>>>(Ahi, Alo, Bhi, Blo, xh1,
                                              s1, d1, as1, ad1, NN, INC);
    cudaStreamWaitEvent(0, evJoin, 0);   // CSR ready before aggregation
    gat_aggregate<<<NN, 256>>>(xh1, s1, d1, ei, b1, h1);

    // ---- BN stats + fused (bn+relu+split) into layer-2 A operand ----
    bn_partial<<<296, 256>>>();
    bn_finalize<<<1, 256>>>(gamma, beta);
    split_h_kernel<<<(NN * HID / 4 + 255) / 256, 256>>>(NN * HID / 4);

    // ---- Layer 2 ----
    gemm_mma<<<ggrid, 256, GEMM_SMEM_BYTES>>>(Ahi, Alo, B2hi, B2lo, xh2,
                                              s2, d2, as2, ad2, NN, HID);
    gat_aggregate<<<NN, 256>>>(xh2, s2, d2, ei, b2, out);
}